// round 3
// baseline (speedup 1.0000x reference)
#include <cuda_runtime.h>
#include <math.h>

#define BB 16
#define PP 500
#define NN 501
#define EE 128
#define HH 8
#define HD 16
#define LL 3
#define LEAKY 0.2f
#define LN_EPS 1e-5f
#define ADJ_CNT (BB * NN * NN)

// Scratch (device globals; no runtime allocation)
__device__ float g_x[2][(size_t)BB * NN * EE];   // ping-pong activations
__device__ float g_xW[(size_t)BB * NN * EE];     // x @ W[l]
__device__ float g_ei[BB * NN * HH];
__device__ float g_ej[BB * NN * HH];
__device__ unsigned char g_adj[ADJ_CNT];         // normalized mask (0/1)
__device__ int g_mask_kind;                      // 0=int32, 1=uint8, 2=float32

// ---------------------------------------------------------------------------
// Kernel 0a: probe mask dtype. One block; scans first 4096 words (safe in all
// layouts since the buffer is >= ADJ_CNT bytes).
// ---------------------------------------------------------------------------
__global__ void probe_mask_kernel(const unsigned int* __restrict__ w) {
    __shared__ int s_u8, s_f32;
    if (threadIdx.x == 0) { s_u8 = 0; s_f32 = 0; }
    __syncthreads();
    for (int idx = threadIdx.x; idx < 4096; idx += blockDim.x) {
        unsigned int v = w[idx];
        if (v == 0x3f800000u) atomicOr(&s_f32, 1);
        else if (v > 1u)      atomicOr(&s_u8, 1);
    }
    __syncthreads();
    if (threadIdx.x == 0)
        g_mask_kind = s_f32 ? 2 : (s_u8 ? 1 : 0);
}

// ---------------------------------------------------------------------------
// Kernel 0b: normalize mask into g_adj (0/1 bytes) regardless of source dtype.
// ---------------------------------------------------------------------------
__global__ void convert_mask_kernel(const void* __restrict__ adj_raw) {
    int i = blockIdx.x * blockDim.x + threadIdx.x;
    if (i >= ADJ_CNT) return;
    int kind = g_mask_kind;
    unsigned char v;
    if (kind == 1) {
        v = ((const unsigned char*)adj_raw)[i] ? 1 : 0;
    } else if (kind == 2) {
        v = (((const float*)adj_raw)[i] != 0.0f) ? 1 : 0;
    } else {
        v = (((const int*)adj_raw)[i] != 0) ? 1 : 0;
    }
    g_adj[i] = v;
}

// ---------------------------------------------------------------------------
// Kernel 1: initial embedding. grid = B*N, block = 128 (one thread per e)
// ---------------------------------------------------------------------------
__global__ void embed_kernel(const float* __restrict__ depot_xy,
                             const float* __restrict__ node5,
                             const float* __restrict__ depW,
                             const float* __restrict__ depb,
                             const float* __restrict__ nodeW,
                             const float* __restrict__ nodeb) {
    int bn = blockIdx.x;            // 0..B*N-1
    int b = bn / NN, n = bn % NN;
    int e = threadIdx.x;
    float v;
    if (n == 0) {
        float x0 = depot_xy[b * 2 + 0];
        float x1 = depot_xy[b * 2 + 1];
        v = fmaf(x0, depW[0 * EE + e], fmaf(x1, depW[1 * EE + e], depb[e]));
    } else {
        int p = n - 1;
        const float* f = node5 + ((size_t)b * PP + p) * 5;
        v = nodeb[e];
        #pragma unroll
        for (int k = 0; k < 5; k++) v = fmaf(f[k], nodeW[k * EE + e], v);
    }
    g_x[0][(size_t)bn * EE + e] = v;
}

// ---------------------------------------------------------------------------
// Kernel 2: xW = x @ W[l]  plus fused ei/ej head projections.
// grid = B*N, block = 128. Thread e computes one output column.
// ---------------------------------------------------------------------------
__global__ void xw_kernel(int src,
                          const float* __restrict__ Wl,
                          const float* __restrict__ attn_l) {
    int bn = blockIdx.x;
    int e = threadIdx.x;
    const float* x = &g_x[src][0];
    __shared__ float xs[EE];
    xs[e] = x[(size_t)bn * EE + e];
    __syncthreads();

    float acc = 0.f;
    #pragma unroll 8
    for (int k = 0; k < EE; k++) acc = fmaf(xs[k], Wl[k * EE + e], acc);
    g_xW[(size_t)bn * EE + e] = acc;

    int h = e >> 4, d = e & 15;
    float vi = acc * attn_l[h * 2 * HD + d];        // a1[h,d]
    float vj = acc * attn_l[h * 2 * HD + HD + d];   // a2[h,d]
    #pragma unroll
    for (int off = 8; off; off >>= 1) {
        vi += __shfl_down_sync(0xffffffffu, vi, off, 16);
        vj += __shfl_down_sync(0xffffffffu, vj, off, 16);
    }
    if (d == 0) {
        g_ei[bn * HH + h] = vi;
        g_ej[bn * HH + h] = vj;
    }
}

// ---------------------------------------------------------------------------
// Kernel 3: masked-softmax attention aggregation + residual + LayerNorm + ELU.
// grid = B*N (one block per output row i), block = 128.
// Thread t owns output element e = t (head h = t/16). Online softmax over
// j-tiles of 16.
// ---------------------------------------------------------------------------
__global__ void attn_kernel(const float* __restrict__ gamma,
                            const float* __restrict__ beta,
                            int dst, float* __restrict__ dout) {
    int bn = blockIdx.x;
    int b = bn / NN, i = bn % NN;
    int t = threadIdx.x;
    int h = t >> 4;

    __shared__ float sh_ei[HH];
    __shared__ float sm[HH], ss[HH], sf[HH];
    __shared__ float pb[16 * HH];
    __shared__ float r1[4], r2[4];
    __shared__ float s_mu, s_rstd;

    if (t < HH) {
        sh_ei[t] = g_ei[bn * HH + t];
        sm[t] = -INFINITY;
        ss[t] = 0.f;
    }
    __syncthreads();

    float acc = 0.f;
    const unsigned char* arow = g_adj + (size_t)b * NN * NN + (size_t)i * NN;
    const float* xWb = g_xW + (size_t)b * NN * EE;

    for (int j0 = 0; j0 < NN; j0 += 16) {
        // --- logits: thread t handles (jj = t>>3, head hh = t&7) ---
        {
            int jj = t >> 3;
            int hh = t & 7;
            int j = j0 + jj;
            float lg = -INFINITY;
            if (j < NN && arow[j]) {
                float v = sh_ei[hh] + g_ej[(b * NN + j) * HH + hh];
                lg = v >= 0.f ? v : LEAKY * v;
            }
            pb[jj * HH + hh] = lg;
        }
        __syncthreads();

        // --- online softmax update: 8 threads, one per head ---
        if (t < HH) {
            float m0 = sm[t];
            float tm = m0;
            #pragma unroll
            for (int jj = 0; jj < 16; jj++) tm = fmaxf(tm, pb[jj * HH + t]);
            if (tm == -INFINITY) {           // fully-masked tile, nothing yet
                sf[t] = 1.f;
                #pragma unroll
                for (int jj = 0; jj < 16; jj++) pb[jj * HH + t] = 0.f;
            } else {
                float f = __expf(m0 - tm);   // m0=-inf -> 0 (zeros stale acc)
                float s = ss[t] * f;
                #pragma unroll
                for (int jj = 0; jj < 16; jj++) {
                    float p = __expf(pb[jj * HH + t] - tm);
                    pb[jj * HH + t] = p;
                    s += p;
                }
                sm[t] = tm; ss[t] = s; sf[t] = f;
            }
        }
        __syncthreads();

        // --- weighted accumulation (coalesced L2 reads of xW rows) ---
        acc *= sf[h];
        #pragma unroll
        for (int jj = 0; jj < 16; jj++) {
            int j = j0 + jj;
            if (j < NN)
                acc = fmaf(pb[jj * HH + h], xWb[(size_t)j * EE + t], acc);
        }
        __syncthreads();   // protect pb before next tile's writes
    }

    // --- normalize, residual, LayerNorm, ELU ---
    float xw = g_xW[(size_t)bn * EE + t];
    float val = acc / ss[h] + xw;

    float s1 = val, s2 = val * val;
    #pragma unroll
    for (int o = 16; o; o >>= 1) {
        s1 += __shfl_down_sync(0xffffffffu, s1, o);
        s2 += __shfl_down_sync(0xffffffffu, s2, o);
    }
    if ((t & 31) == 0) { r1[t >> 5] = s1; r2[t >> 5] = s2; }
    __syncthreads();
    if (t == 0) {
        float a = r1[0] + r1[1] + r1[2] + r1[3];
        float q = r2[0] + r2[1] + r2[2] + r2[3];
        float mu = a * (1.f / EE);
        float var = q * (1.f / EE) - mu * mu;
        s_mu = mu;
        s_rstd = rsqrtf(var + LN_EPS);
    }
    __syncthreads();

    float y = (val - s_mu) * s_rstd * gamma[t] + beta[t];
    y = y > 0.f ? y : expm1f(y);

    float* o = (dst < 0) ? dout : &g_x[dst][0];
    o[(size_t)bn * EE + t] = y;
}

// ---------------------------------------------------------------------------
extern "C" void kernel_launch(void* const* d_in, const int* in_sizes, int n_in,
                              void* d_out, int out_size) {
    const float* depot_xy = (const float*)d_in[0];
    const float* node5    = (const float*)d_in[1];
    const void*  adj_raw  = (const void*)d_in[2];
    const float* depW  = (const float*)d_in[3];
    const float* depb  = (const float*)d_in[4];
    const float* nodeW = (const float*)d_in[5];
    const float* nodeb = (const float*)d_in[6];
    const float* W     = (const float*)d_in[7];   // [L,E,E]
    const float* attn  = (const float*)d_in[8];   // [L,H,2*HD]
    const float* ln_g  = (const float*)d_in[9];   // [L,E]
    const float* ln_b  = (const float*)d_in[10];  // [L,E]
    float* out = (float*)d_out;

    probe_mask_kernel<<<1, 256>>>((const unsigned int*)adj_raw);
    convert_mask_kernel<<<(ADJ_CNT + 255) / 256, 256>>>(adj_raw);

    dim3 grid(BB * NN);
    embed_kernel<<<grid, EE>>>(depot_xy, node5, depW, depb, nodeW, nodeb);

    int cur = 0;
    for (int l = 0; l < LL; l++) {
        xw_kernel<<<grid, EE>>>(cur,
                                W + (size_t)l * EE * EE,
                                attn + (size_t)l * HH * 2 * HD);
        int dst = (l == LL - 1) ? -1 : (1 - cur);
        attn_kernel<<<grid, EE>>>(ln_g + (size_t)l * EE,
                                  ln_b + (size_t)l * EE,
                                  dst, out);
        cur = 1 - cur;
    }
}

// round 4
// speedup vs baseline: 1.7305x; 1.7305x over previous
#include <cuda_runtime.h>
#include <math.h>

#define BB 16
#define PP 500
#define NN 501
#define EE 128
#define HH 8
#define HD 16
#define LL 3
#define LEAKY 0.2f
#define LN_EPS 1e-5f
#define ADJ_CNT (BB * NN * NN)
#define IT 16
#define JT 16

// Scratch (device globals; no runtime allocation)
__device__ float g_x[2][(size_t)BB * NN * EE];   // ping-pong activations
__device__ float g_xW[(size_t)BB * NN * EE];     // x @ W[l]
__device__ float g_ei[BB * NN * HH];
__device__ float g_ej[BB * NN * HH];
__device__ unsigned char g_adj[ADJ_CNT];         // normalized mask (0/1)
__device__ int g_mask_kind;                      // 0=int32, 1=uint8, 2=float32

// ---------------------------------------------------------------------------
// Kernel 0a: probe mask dtype (bool-as-int32 vs uint8 vs float32).
// ---------------------------------------------------------------------------
__global__ void probe_mask_kernel(const unsigned int* __restrict__ w) {
    __shared__ int s_u8, s_f32;
    if (threadIdx.x == 0) { s_u8 = 0; s_f32 = 0; }
    __syncthreads();
    for (int idx = threadIdx.x; idx < 4096; idx += blockDim.x) {
        unsigned int v = w[idx];
        if (v == 0x3f800000u) atomicOr(&s_f32, 1);
        else if (v > 1u)      atomicOr(&s_u8, 1);
    }
    __syncthreads();
    if (threadIdx.x == 0)
        g_mask_kind = s_f32 ? 2 : (s_u8 ? 1 : 0);
}

// ---------------------------------------------------------------------------
// Kernel 0b: normalize mask into g_adj (0/1 bytes).
// ---------------------------------------------------------------------------
__global__ void convert_mask_kernel(const void* __restrict__ adj_raw) {
    int i = blockIdx.x * blockDim.x + threadIdx.x;
    if (i >= ADJ_CNT) return;
    int kind = g_mask_kind;
    unsigned char v;
    if (kind == 1)      v = ((const unsigned char*)adj_raw)[i] ? 1 : 0;
    else if (kind == 2) v = (((const float*)adj_raw)[i] != 0.0f) ? 1 : 0;
    else                v = (((const int*)adj_raw)[i] != 0) ? 1 : 0;
    g_adj[i] = v;
}

// ---------------------------------------------------------------------------
// Kernel 1: initial embedding. grid = B*N, block = 128
// ---------------------------------------------------------------------------
__global__ void embed_kernel(const float* __restrict__ depot_xy,
                             const float* __restrict__ node5,
                             const float* __restrict__ depW,
                             const float* __restrict__ depb,
                             const float* __restrict__ nodeW,
                             const float* __restrict__ nodeb) {
    int bn = blockIdx.x;
    int b = bn / NN, n = bn % NN;
    int e = threadIdx.x;
    float v;
    if (n == 0) {
        float x0 = depot_xy[b * 2 + 0];
        float x1 = depot_xy[b * 2 + 1];
        v = fmaf(x0, depW[0 * EE + e], fmaf(x1, depW[1 * EE + e], depb[e]));
    } else {
        int p = n - 1;
        const float* f = node5 + ((size_t)b * PP + p) * 5;
        v = nodeb[e];
        #pragma unroll
        for (int k = 0; k < 5; k++) v = fmaf(f[k], nodeW[k * EE + e], v);
    }
    g_x[0][(size_t)bn * EE + e] = v;
}

// ---------------------------------------------------------------------------
// Kernel 2: row-tiled xW = x @ W[l] + fused ei/ej head projections.
// grid = B*N/16 = 501 blocks, block = 256. Thread: e = t&127, owns 8 rows.
// W column loads are reused 16x within the block (L1-resident).
// ---------------------------------------------------------------------------
__global__ void __launch_bounds__(256) xw_kernel(int src,
                                                const float* __restrict__ Wl,
                                                const float* __restrict__ attn_l) {
    int t = threadIdx.x;
    int e = t & 127, half = t >> 7;
    int row0 = blockIdx.x * 16;           // B*N = 8016 = 501*16, exact
    __shared__ float xs[16][EE];
    const float* x = &g_x[src][0];
    {
        const float4* s4 = (const float4*)(x + (size_t)row0 * EE);
        float4* d4 = (float4*)&xs[0][0];
        for (int idx = t; idx < 16 * EE / 4; idx += 256) d4[idx] = s4[idx];
    }
    __syncthreads();

    float acc[8];
    #pragma unroll
    for (int r = 0; r < 8; r++) acc[r] = 0.f;

    for (int k = 0; k < EE; k += 4) {
        float w0 = Wl[(k + 0) * EE + e];
        float w1 = Wl[(k + 1) * EE + e];
        float w2 = Wl[(k + 2) * EE + e];
        float w3 = Wl[(k + 3) * EE + e];
        #pragma unroll
        for (int r = 0; r < 8; r++) {
            float4 xv = *(const float4*)&xs[half * 8 + r][k];
            acc[r] = fmaf(xv.x, w0, acc[r]);
            acc[r] = fmaf(xv.y, w1, acc[r]);
            acc[r] = fmaf(xv.z, w2, acc[r]);
            acc[r] = fmaf(xv.w, w3, acc[r]);
        }
    }

    int h = e >> 4, d = e & 15;
    float a1 = attn_l[h * 2 * HD + d];
    float a2 = attn_l[h * 2 * HD + HD + d];
    #pragma unroll
    for (int r = 0; r < 8; r++) {
        int row = row0 + half * 8 + r;
        g_xW[(size_t)row * EE + e] = acc[r];
        float vi = acc[r] * a1, vj = acc[r] * a2;
        #pragma unroll
        for (int off = 8; off; off >>= 1) {
            vi += __shfl_down_sync(0xffffffffu, vi, off, 16);
            vj += __shfl_down_sync(0xffffffffu, vj, off, 16);
        }
        if (d == 0) { g_ei[row * HH + h] = vi; g_ej[row * HH + h] = vj; }
    }
}

// ---------------------------------------------------------------------------
// Kernel 3: i-tiled attention + residual + LayerNorm + ELU.
// grid = (ceil(N/16)=32, B), block = 256.
// Two-pass softmax: m = leaky(ei + max_adj ej) (leaky is monotone), then a
// single streaming pass with unnormalized accumulation; s gathered by one
// lane per (i,h). xW j-rows staged through smem, reused by 16 i-rows.
// ---------------------------------------------------------------------------
__global__ void __launch_bounds__(256) attn_kernel(const float* __restrict__ gamma,
                                                   const float* __restrict__ beta,
                                                   int dst, float* __restrict__ dout) {
    int b = blockIdx.y;
    int i0 = blockIdx.x * IT;
    int t = threadIdx.x;

    __shared__ float ej_s[NN * HH];          // 16032 B
    __shared__ float ei_s[IT * HH];
    __shared__ float m_s[IT * HH];
    __shared__ float mred[2][IT * HH];
    __shared__ float s_s[IT * HH];
    __shared__ unsigned char mask_s[IT * NN]; // 8016 B
    __shared__ float xs[JT][EE];              // 8192 B
    __shared__ float p_s[JT][IT * HH];        // 8192 B
    __shared__ float lnred[8][4][2];

    const float* xWb = g_xW + (size_t)b * NN * EE;

    for (int idx = t; idx < NN * HH; idx += 256) ej_s[idx] = g_ej[b * NN * HH + idx];
    for (int idx = t; idx < IT * HH; idx += 256) {
        int i = i0 + (idx >> 3);
        ei_s[idx] = (i < NN) ? g_ei[(b * NN + i) * HH + (idx & 7)] : 0.f;
    }
    const unsigned char* adjb = g_adj + (size_t)b * NN * NN;
    #pragma unroll
    for (int r = 0; r < IT; r++) {
        int i = i0 + r;
        for (int c2 = t; c2 < NN; c2 += 256)
            mask_s[r * NN + c2] = (i < NN) ? adjb[(size_t)i * NN + c2] : 0;
    }
    __syncthreads();

    // Pass A: m[i,h] = leaky(ei + max_{adj j} ej[j,h])
    {
        int p = t & 127, half = t >> 7;
        int ii = p >> 3, hh = p & 7;
        int jb = half ? 251 : 0, je = half ? NN : 251;
        float mx = -INFINITY;
        for (int j = jb; j < je; j++)
            if (mask_s[ii * NN + j]) mx = fmaxf(mx, ej_s[j * HH + hh]);
        mred[half][p] = mx;
    }
    __syncthreads();
    if (t < IT * HH) {
        float v = fmaxf(mred[0][t], mred[1][t]);
        float w = ei_s[t] + v;
        m_s[t] = (w >= 0.f) ? w : LEAKY * w;
    }
    __syncthreads();

    // Pass B: streaming accumulation.
    int c = t & 63;          // float2 column: e = 2c
    int grp = t >> 6;        // i-group: rows grp*4..grp*4+3
    int h = c >> 3;
    float2 acc[4];
    float sacc[4];
    #pragma unroll
    for (int r = 0; r < 4; r++) { acc[r] = make_float2(0.f, 0.f); sacc[r] = 0.f; }
    bool sowner = ((c & 7) == 0);

    for (int j0 = 0; j0 < NN; j0 += JT) {
        // stage xW j-tile
        {
            float4* d4 = (float4*)&xs[0][0];
            for (int idx = t; idx < JT * EE / 4; idx += 256) {
                int jj = idx >> 5;
                int j = j0 + jj;
                d4[idx] = (j < NN) ? ((const float4*)(xWb + (size_t)j * EE))[idx & 31]
                                   : make_float4(0.f, 0.f, 0.f, 0.f);
            }
        }
        // p = exp(leaky(ei+ej) - m) for this tile (0 where masked)
        for (int idx = t; idx < JT * IT * HH; idx += 256) {
            int jj = idx >> 7, ph = idx & 127;
            int ii = ph >> 3, hh = ph & 7;
            int j = j0 + jj;
            float val = 0.f;
            if (j < NN && mask_s[ii * NN + j]) {
                float w = ei_s[ph] + ej_s[j * HH + hh];
                w = (w >= 0.f) ? w : LEAKY * w;
                val = __expf(w - m_s[ph]);
            }
            p_s[jj][ph] = val;
        }
        __syncthreads();
        #pragma unroll 4
        for (int jj = 0; jj < JT; jj++) {
            float2 xv = *(const float2*)&xs[jj][2 * c];
            #pragma unroll
            for (int r = 0; r < 4; r++) {
                float pv = p_s[jj][(grp * 4 + r) * HH + h];
                acc[r].x = fmaf(pv, xv.x, acc[r].x);
                acc[r].y = fmaf(pv, xv.y, acc[r].y);
                if (sowner) sacc[r] += pv;
            }
        }
        __syncthreads();
    }

    if (sowner) {
        #pragma unroll
        for (int r = 0; r < 4; r++) s_s[(grp * 4 + r) * HH + h] = sacc[r];
    }
    __syncthreads();

    // epilogue: normalize, residual, LayerNorm, ELU
    float2 val[4];
    float s1[4], s2[4];
    #pragma unroll
    for (int r = 0; r < 4; r++) {
        int ii = grp * 4 + r;
        int i = i0 + ii;
        float sv = s_s[ii * HH + h];
        float2 xwv = (i < NN) ? *(const float2*)(xWb + (size_t)i * EE + 2 * c)
                              : make_float2(0.f, 0.f);
        float inv = 1.f / sv;
        val[r].x = acc[r].x * inv + xwv.x;
        val[r].y = acc[r].y * inv + xwv.y;
        s1[r] = val[r].x + val[r].y;
        s2[r] = val[r].x * val[r].x + val[r].y * val[r].y;
    }
    #pragma unroll
    for (int off = 16; off; off >>= 1) {
        #pragma unroll
        for (int r = 0; r < 4; r++) {
            s1[r] += __shfl_down_sync(0xffffffffu, s1[r], off);
            s2[r] += __shfl_down_sync(0xffffffffu, s2[r], off);
        }
    }
    int warp = t >> 5;
    if ((t & 31) == 0) {
        #pragma unroll
        for (int r = 0; r < 4; r++) { lnred[warp][r][0] = s1[r]; lnred[warp][r][1] = s2[r]; }
    }
    __syncthreads();

    float* o = (dst < 0) ? dout : &g_x[dst][0];
    int w0 = grp * 2;
    float gx = gamma[2 * c], gy = gamma[2 * c + 1];
    float bx = beta[2 * c],  by = beta[2 * c + 1];
    #pragma unroll
    for (int r = 0; r < 4; r++) {
        int ii = grp * 4 + r;
        int i = i0 + ii;
        if (i >= NN) continue;
        float a = lnred[w0][r][0] + lnred[w0 + 1][r][0];
        float q = lnred[w0][r][1] + lnred[w0 + 1][r][1];
        float mu = a * (1.f / EE);
        float var = q * (1.f / EE) - mu * mu;
        float rstd = rsqrtf(var + LN_EPS);
        float yx = (val[r].x - mu) * rstd * gx + bx;
        float yy = (val[r].y - mu) * rstd * gy + by;
        yx = yx > 0.f ? yx : expm1f(yx);
        yy = yy > 0.f ? yy : expm1f(yy);
        *(float2*)(o + ((size_t)(b * NN + i)) * EE + 2 * c) = make_float2(yx, yy);
    }
}

// ---------------------------------------------------------------------------
extern "C" void kernel_launch(void* const* d_in, const int* in_sizes, int n_in,
                              void* d_out, int out_size) {
    const float* depot_xy = (const float*)d_in[0];
    const float* node5    = (const float*)d_in[1];
    const void*  adj_raw  = (const void*)d_in[2];
    const float* depW  = (const float*)d_in[3];
    const float* depb  = (const float*)d_in[4];
    const float* nodeW = (const float*)d_in[5];
    const float* nodeb = (const float*)d_in[6];
    const float* W     = (const float*)d_in[7];   // [L,E,E]
    const float* attn  = (const float*)d_in[8];   // [L,H,2*HD]
    const float* ln_g  = (const float*)d_in[9];   // [L,E]
    const float* ln_b  = (const float*)d_in[10];  // [L,E]
    float* out = (float*)d_out;

    probe_mask_kernel<<<1, 256>>>((const unsigned int*)adj_raw);
    convert_mask_kernel<<<(ADJ_CNT + 255) / 256, 256>>>(adj_raw);

    embed_kernel<<<BB * NN, EE>>>(depot_xy, node5, depW, depb, nodeW, nodeb);

    dim3 agrid((NN + IT - 1) / IT, BB);
    int cur = 0;
    for (int l = 0; l < LL; l++) {
        xw_kernel<<<BB * NN / 16, 256>>>(cur,
                                         W + (size_t)l * EE * EE,
                                         attn + (size_t)l * HH * 2 * HD);
        int dst = (l == LL - 1) ? -1 : (1 - cur);
        attn_kernel<<<agrid, 256>>>(ln_g + (size_t)l * EE,
                                    ln_b + (size_t)l * EE,
                                    dst, out);
        cur = 1 - cur;
    }
}